// round 1
// baseline (speedup 1.0000x reference)
#include <cuda_runtime.h>
#include <math.h>

// Problem constants (fixed shapes from reference)
#define BB 2
#define NN 262144
#define KK 9     // K+1 slots
#define DD 64
#define SS 64
static __device__ __constant__ float kSCALE = 0.125f;   // 64^-0.5
#define BG_BOUND 1.0f

// Precomputed per-batch slot-side operands (folded projections)
__device__ __align__(16) float g_K[BB][KK][DD];   // k = slots_full @ Wk^T + Wk_b
__device__ __align__(16) float g_M[BB][KK][DD];   // M[j][e] = sum_d k[j][d]*Wq[d][e]
__device__ __align__(16) float g_P[BB][KK][DD];   // P[j][d] = sum_s sf[j][s]*out_w[d][s]
__device__ float g_c[BB][KK];                     // c[j]    = Wq_b . k[j]

// ---------------------------------------------------------------------------
// Precompute 1: k-slots and P (both only need slots_full)
// ---------------------------------------------------------------------------
__global__ void precompute1(const float* __restrict__ slots,
                            const float* __restrict__ empty_slot,
                            const float* __restrict__ Wk_w,
                            const float* __restrict__ Wk_b,
                            const float* __restrict__ out_w)
{
    int b = blockIdx.x;
    int t = threadIdx.x;
    if (t >= KK * DD) return;
    int j = t / DD, d = t % DD;
    const float* sf = (j == 0) ? empty_slot
                               : slots + ((size_t)b * (KK - 1) + (j - 1)) * SS;
    float kk = Wk_b[d];
    float pp = 0.f;
#pragma unroll 8
    for (int s = 0; s < SS; s++) {
        float sv = sf[s];
        kk = fmaf(sv, Wk_w[d * SS + s], kk);
        pp = fmaf(sv, out_w[d * SS + s], pp);
    }
    g_K[b][j][d] = kk;
    g_P[b][j][d] = pp;
}

// ---------------------------------------------------------------------------
// Precompute 2: M = K @ Wq, c = K @ Wq_b (needs g_K from precompute1)
// ---------------------------------------------------------------------------
__global__ void precompute2(const float* __restrict__ Wq_w,
                            const float* __restrict__ Wq_b)
{
    int b = blockIdx.x;
    int t = threadIdx.x;
    if (t >= KK * DD) return;
    int j = t / DD, e = t % DD;
    float m = 0.f;
#pragma unroll 8
    for (int d = 0; d < DD; d++)
        m = fmaf(g_K[b][j][d], Wq_w[d * DD + e], m);
    g_M[b][j][e] = m;
    if (e == 0) {
        float cc = 0.f;
        for (int d = 0; d < DD; d++)
            cc = fmaf(Wq_b[d], g_K[b][j][d], cc);
        g_c[b][j] = cc;
    }
}

// ---------------------------------------------------------------------------
// Main kernel: one thread per point
// ---------------------------------------------------------------------------
__global__ __launch_bounds__(256)
void joint_decoder_main(const float* __restrict__ pf,
                        const float* __restrict__ coor,
                        const float* __restrict__ out_b,
                        const float* __restrict__ dscale,
                        float* __restrict__ xo,
                        float* __restrict__ wout,
                        float* __restrict__ sig)
{
    __shared__ float4 sM[KK][DD / 4];
    __shared__ float4 sP[KK][DD / 4];
    __shared__ float4 sOb[DD / 4];
    __shared__ float  sC[KK];
    __shared__ float  sDs;

    const int tid = threadIdx.x;
    const int p0  = blockIdx.x * 256;
    const int b   = p0 / NN;            // block never straddles a batch (N % 256 == 0)

    // Cooperative shared-memory staging (144 float4 each for M and P)
    const float4* gM4 = reinterpret_cast<const float4*>(&g_M[b][0][0]);
    const float4* gP4 = reinterpret_cast<const float4*>(&g_P[b][0][0]);
    if (tid < KK * (DD / 4)) {
        (&sM[0][0])[tid] = gM4[tid];
        (&sP[0][0])[tid] = gP4[tid];
    }
    if (tid >= 224 && tid < 224 + DD / 4)
        sOb[tid - 224] = reinterpret_cast<const float4*>(out_b)[tid - 224];
    if (tid >= 208 && tid < 208 + KK) sC[tid - 208] = g_c[b][tid - 208];
    if (tid == 255) sDs = __expf(dscale[0]);
    __syncthreads();

    const int p = p0 + tid;

    // ---- logits: 9 dot-products of length 64 ----
    const float4* xv = reinterpret_cast<const float4*>(pf + (size_t)p * DD);
    float acc[KK];
#pragma unroll
    for (int j = 0; j < KK; j++) acc[j] = 0.f;
#pragma unroll
    for (int i = 0; i < DD / 4; i++) {
        const float4 x = xv[i];
#pragma unroll
        for (int j = 0; j < KK; j++) {
            const float4 m = sM[j][i];
            acc[j] = fmaf(x.x, m.x,
                     fmaf(x.y, m.y,
                     fmaf(x.z, m.z,
                     fmaf(x.w, m.w, acc[j]))));
        }
    }

    float logit[KK];
#pragma unroll
    for (int j = 0; j < KK; j++) logit[j] = (acc[j] + sC[j]) * kSCALE;

    // ---- force_bg mask ----
    const float* cp = coor + (size_t)p * 3;
    const float c0 = cp[0], c1 = cp[1], c2 = cp[2];
    const bool inb = (fabsf(c0) <= BG_BOUND) && (fabsf(c1) <= BG_BOUND) &&
                     (fabsf(c2) <= BG_BOUND);

    // ---- softmax over allowed slots ----
    float mx = fmaxf(logit[0], logit[1]);
    if (inb) {
#pragma unroll
        for (int j = 2; j < KK; j++) mx = fmaxf(mx, logit[j]);
    }
    float w[KK];
    w[0] = __expf(logit[0] - mx);
    w[1] = __expf(logit[1] - mx);
    float s = w[0] + w[1];
#pragma unroll
    for (int j = 2; j < KK; j++) {
        const float e = inb ? __expf(logit[j] - mx) : 0.f;
        w[j] = e;
        s += e;
    }
    const float inv = __frcp_rn(s);
#pragma unroll
    for (int j = 0; j < KK; j++) w[j] *= inv;

    // ---- density: sum_{j>=1} relu(logit[j]) * w[j] (masked w are exactly 0) ----
    float sg = 0.f;
#pragma unroll
    for (int j = 1; j < KK; j++) sg = fmaf(fmaxf(logit[j], 0.f), w[j], sg);

    // ---- xo = w @ P + out_b ----
    float4* xov = reinterpret_cast<float4*>(xo + (size_t)p * DD);
#pragma unroll
    for (int i = 0; i < DD / 4; i++) {
        float4 o = sOb[i];
#pragma unroll
        for (int j = 0; j < KK; j++) {
            const float4 pv = sP[j][i];
            o.x = fmaf(w[j], pv.x, o.x);
            o.y = fmaf(w[j], pv.y, o.y);
            o.z = fmaf(w[j], pv.z, o.z);
            o.w = fmaf(w[j], pv.w, o.w);
        }
        xov[i] = o;
    }

    // ---- w and sigma outputs ----
    float* wp = wout + (size_t)p * KK;
#pragma unroll
    for (int j = 0; j < KK; j++) wp[j] = w[j];
    sig[p] = sg * sDs;
}

// ---------------------------------------------------------------------------
// Launch
// ---------------------------------------------------------------------------
extern "C" void kernel_launch(void* const* d_in, const int* in_sizes, int n_in,
                              void* d_out, int out_size)
{
    const float* pf     = (const float*)d_in[0];   // point_feats [B,N,D]
    // d_in[1] = points_emb — unused by the reference math, never read
    const float* slots  = (const float*)d_in[2];   // [B,K,S]
    const float* coor   = (const float*)d_in[3];   // [B,N,3]
    const float* empty  = (const float*)d_in[4];   // [1,1,S]
    const float* Wq_w   = (const float*)d_in[5];   // [D,D]
    const float* Wq_b   = (const float*)d_in[6];   // [D]
    const float* Wk_w   = (const float*)d_in[7];   // [D,S]
    const float* Wk_b   = (const float*)d_in[8];   // [D]
    const float* out_w  = (const float*)d_in[9];   // [D,S]
    const float* out_b  = (const float*)d_in[10];  // [D]
    const float* dscale = (const float*)d_in[11];  // [1]
    // d_in[12] = Nr (unused)

    float* out  = (float*)d_out;
    float* xo   = out;                                  // [B,N,64]
    float* wout = out + (size_t)BB * NN * DD;           // [B,N,9]
    float* sig  = wout + (size_t)BB * NN * KK;          // [B,N]

    precompute1<<<BB, 576>>>(slots, empty, Wk_w, Wk_b, out_w);
    precompute2<<<BB, 576>>>(Wq_w, Wq_b);
    joint_decoder_main<<<(BB * NN) / 256, 256>>>(pf, coor, out_b, dscale,
                                                 xo, wout, sig);
}

// round 3
// speedup vs baseline: 1.0775x; 1.0775x over previous
#include <cuda_runtime.h>
#include <math.h>

#define BB 2
#define NN 262144
#define KK 9      // K+1 slots
#define DD 64
#define SS 64
#define BG_BOUND 1.0f
#define SCALE_F 0.125f

// Precomputed per-batch folded operands
__device__ __align__(16) float g_M[BB][KK][DD];   // M = K @ Wq     (logit matrix)
__device__ __align__(16) float g_P[BB][KK][DD];   // P = slots_full @ out_w^T
__device__ float g_c[BB][KK];                     // c = K @ Wq_b

// ---------------------------------------------------------------------------
// Packed fp32x2 helpers (Blackwell fma.rn.f32x2)
// ---------------------------------------------------------------------------
typedef unsigned long long f2_t;
__device__ __forceinline__ f2_t fma2(f2_t a, f2_t b, f2_t c) {
    f2_t d;
    asm("fma.rn.f32x2 %0, %1, %2, %3;" : "=l"(d) : "l"(a), "l"(b), "l"(c));
    return d;
}
__device__ __forceinline__ f2_t pack2(float lo, float hi) {
    f2_t d;
    asm("mov.b64 %0, {%1, %2};" : "=l"(d) : "f"(lo), "f"(hi));
    return d;
}
__device__ __forceinline__ float2 unpack2(f2_t v) {
    float2 r;
    asm("mov.b64 {%0, %1}, %2;" : "=f"(r.x), "=f"(r.y) : "l"(v));
    return r;
}

// ---------------------------------------------------------------------------
// Fused precompute: one block per batch, 576 threads.
// Stage weights coalesced into padded shared, then random-access from SMEM.
// ---------------------------------------------------------------------------
__global__ __launch_bounds__(576)
void precompute_fused(const float* __restrict__ slots,
                      const float* __restrict__ empty_slot,
                      const float* __restrict__ Wq_w,
                      const float* __restrict__ Wq_b,
                      const float* __restrict__ Wk_w,
                      const float* __restrict__ Wk_b,
                      const float* __restrict__ out_w)
{
    __shared__ float sWk[DD][SS + 1];   // padded: conflict-free row walks
    __shared__ float sOw[DD][SS + 1];
    __shared__ float sSlot[KK][SS];
    __shared__ float sK[KK][DD];

    const int b = blockIdx.x;
    const int t = threadIdx.x;

    // Coalesced staging of Wk_w and out_w (4096 floats each)
    for (int i = t; i < DD * SS; i += 576) {
        int r = i >> 6, c = i & 63;
        sWk[r][c] = Wk_w[i];
        sOw[r][c] = out_w[i];
    }
    {   // slots_full [9][64]
        int j = t / SS, s = t % SS;
        sSlot[j][s] = (j == 0) ? empty_slot[s]
                               : slots[((size_t)b * (KK - 1) + (j - 1)) * SS + s];
    }
    __syncthreads();

    const int j = t / DD, d = t % DD;
    float kk = Wk_b[d];
    float pp = 0.f;
#pragma unroll 8
    for (int s = 0; s < SS; s++) {
        const float sv = sSlot[j][s];      // broadcast
        kk = fmaf(sv, sWk[d][s], kk);      // padded -> conflict-free
        pp = fmaf(sv, sOw[d][s], pp);
    }
    sK[j][d] = kk;
    g_P[b][j][d] = pp;
    __syncthreads();

    // M[j][e] = sum_d K[j][d] * Wq[d][e]  (Wq_w coalesced across lanes)
    const int e = d;
    float m = 0.f;
#pragma unroll 8
    for (int dd = 0; dd < DD; dd++)
        m = fmaf(sK[j][dd], Wq_w[dd * DD + e], m);
    g_M[b][j][e] = m;

    if (e == 0) {
        float cc = 0.f;
        for (int dd = 0; dd < DD; dd++)
            cc = fmaf(Wq_b[dd], sK[j][dd], cc);
        g_c[b][j] = cc;
    }
}

// ---------------------------------------------------------------------------
// Main kernel: one thread per point, packed-f32x2 math, staged I/O
// ---------------------------------------------------------------------------
__global__ __launch_bounds__(256)
void joint_decoder_main(const float* __restrict__ pf,
                        const float* __restrict__ coor,
                        const float* __restrict__ out_b,
                        const float* __restrict__ dscale,
                        float* __restrict__ xo,
                        float* __restrict__ wout,
                        float* __restrict__ sig)
{
    __shared__ ulonglong2 sM2[KK][DD / 4];   // 16B = 2 packed f32x2
    __shared__ ulonglong2 sP2[KK][DD / 4];
    __shared__ ulonglong2 sOb2[DD / 4];
    __shared__ float      sC[KK];
    __shared__ float      sDs;
    __shared__ float4     sCoor4[192];       // 256 pts * 3 floats
    __shared__ float      sW[256 * KK];      // staged w for coalesced stores

    const int tid = threadIdx.x;
    const int p0  = blockIdx.x * 256;
    const int b   = p0 / NN;                 // blocks never straddle batches

    // ---- cooperative staging ----
    if (tid < KK * (DD / 4)) {
        (&sM2[0][0])[tid] = reinterpret_cast<const ulonglong2*>(&g_M[b][0][0])[tid];
        (&sP2[0][0])[tid] = reinterpret_cast<const ulonglong2*>(&g_P[b][0][0])[tid];
    } else if (tid < 144 + DD / 4) {
        sOb2[tid - 144] = reinterpret_cast<const ulonglong2*>(out_b)[tid - 144];
    } else if (tid < 160 + KK) {
        sC[tid - 160] = g_c[b][tid - 160];
    } else if (tid == 170) {
        sDs = __expf(dscale[0]);
    }
    if (tid >= 64)   // 192 threads stage coords (float4-coalesced)
        sCoor4[tid - 64] =
            reinterpret_cast<const float4*>(coor + (size_t)p0 * 3)[tid - 64];
    __syncthreads();

    const int p = p0 + tid;

    // ---- logits: 9 dot-64s in packed f32x2 ----
    const ulonglong2* xv = reinterpret_cast<const ulonglong2*>(pf + (size_t)p * DD);
    f2_t acc[KK];
#pragma unroll
    for (int j = 0; j < KK; j++) acc[j] = 0ULL;   // (+0.0f, +0.0f)
#pragma unroll
    for (int i = 0; i < DD / 4; i++) {
        const ulonglong2 x = xv[i];
#pragma unroll
        for (int j = 0; j < KK; j++) {
            const ulonglong2 m = sM2[j][i];       // broadcast LDS.128
            acc[j] = fma2(x.x, m.x, acc[j]);
            acc[j] = fma2(x.y, m.y, acc[j]);
        }
    }
    float logit[KK];
#pragma unroll
    for (int j = 0; j < KK; j++) {
        const float2 a = unpack2(acc[j]);
        logit[j] = (a.x + a.y + sC[j]) * SCALE_F;
    }

    // ---- force_bg mask ----
    const float* cp = reinterpret_cast<const float*>(sCoor4) + tid * 3;
    const bool inb = (fabsf(cp[0]) <= BG_BOUND) && (fabsf(cp[1]) <= BG_BOUND) &&
                     (fabsf(cp[2]) <= BG_BOUND);

    // ---- masked softmax ----
    float mx = fmaxf(logit[0], logit[1]);
    if (inb) {
#pragma unroll
        for (int j = 2; j < KK; j++) mx = fmaxf(mx, logit[j]);
    }
    float w[KK];
    w[0] = __expf(logit[0] - mx);
    w[1] = __expf(logit[1] - mx);
    float s = w[0] + w[1];
#pragma unroll
    for (int j = 2; j < KK; j++) {
        const float e = inb ? __expf(logit[j] - mx) : 0.f;
        w[j] = e;
        s += e;
    }
    const float inv = __frcp_rn(s);
#pragma unroll
    for (int j = 0; j < KK; j++) w[j] *= inv;

    // ---- density ----
    float sg = 0.f;
#pragma unroll
    for (int j = 1; j < KK; j++) sg = fmaf(fmaxf(logit[j], 0.f), w[j], sg);

    // ---- xo = w @ P + out_b (packed) ----
    f2_t ww[KK];
#pragma unroll
    for (int j = 0; j < KK; j++) ww[j] = pack2(w[j], w[j]);

    ulonglong2* xov = reinterpret_cast<ulonglong2*>(xo + (size_t)p * DD);
#pragma unroll
    for (int i = 0; i < DD / 4; i++) {
        ulonglong2 o = sOb2[i];
#pragma unroll
        for (int j = 0; j < KK; j++) {
            const ulonglong2 pv = sP2[j][i];
            o.x = fma2(ww[j], pv.x, o.x);
            o.y = fma2(ww[j], pv.y, o.y);
        }
        xov[i] = o;
    }

    // ---- w out: stage in shared, store float4-coalesced ----
#pragma unroll
    for (int j = 0; j < KK; j++) sW[tid * KK + j] = w[j];   // gcd(9,32)=1: no conflicts
    sig[p] = sg * sDs;
    __syncthreads();
    {
        const float4* sw4 = reinterpret_cast<const float4*>(sW);
        float4* wg4 = reinterpret_cast<float4*>(wout + (size_t)p0 * KK);
#pragma unroll
        for (int i = tid; i < (256 * KK) / 4; i += 256)
            wg4[i] = sw4[i];
    }
}

// ---------------------------------------------------------------------------
// Launch
// ---------------------------------------------------------------------------
extern "C" void kernel_launch(void* const* d_in, const int* in_sizes, int n_in,
                              void* d_out, int out_size)
{
    const float* pf     = (const float*)d_in[0];   // point_feats [B,N,D]
    const float* slots  = (const float*)d_in[2];   // [B,K,S]
    const float* coor   = (const float*)d_in[3];   // [B,N,3]
    const float* empty  = (const float*)d_in[4];   // [1,1,S]
    const float* Wq_w   = (const float*)d_in[5];
    const float* Wq_b   = (const float*)d_in[6];
    const float* Wk_w   = (const float*)d_in[7];
    const float* Wk_b   = (const float*)d_in[8];
    const float* out_w  = (const float*)d_in[9];
    const float* out_b  = (const float*)d_in[10];
    const float* dscale = (const float*)d_in[11];

    float* out  = (float*)d_out;
    float* xo   = out;                              // [B,N,64]
    float* wout = out + (size_t)BB * NN * DD;       // [B,N,9]
    float* sig  = wout + (size_t)BB * NN * KK;      // [B,N]

    precompute_fused<<<BB, 576>>>(slots, empty, Wq_w, Wq_b, Wk_w, Wk_b, out_w);
    joint_decoder_main<<<(BB * NN) / 256, 256>>>(pf, coor, out_b, dscale,
                                                 xo, wout, sig);
}

// round 6
// speedup vs baseline: 1.3892x; 1.2893x over previous
#include <cuda_runtime.h>
#include <math.h>

#define BB 2
#define NN 262144
#define KK 9      // K+1 slots
#define DD 64
#define SS 64
#define BG_BOUND 1.0f
#define SCALE_F 0.125f

// ---------------------------------------------------------------------------
// Folded per-batch operands, computed on device then copied into __constant__
// so the main kernel reads them via the constant port (separate from L1tex).
// ---------------------------------------------------------------------------
struct __align__(16) PreData {
    float M[BB][KK][DD];   // M = K @ Wq          (logit matrix)
    float P[BB][KK][DD];   // P = slots_full @ out_w^T
    float c[BB][KK];       // c = K @ Wq_b
    float ob[DD];          // out_b
    float ds;              // exp(density_scale)
};
__device__    PreData g_pre;
__constant__  PreData c_pre;

// ---------------------------------------------------------------------------
// Packed fp32x2 helpers (Blackwell fma.rn.f32x2)
// ---------------------------------------------------------------------------
typedef unsigned long long f2_t;
__device__ __forceinline__ f2_t fma2(f2_t a, f2_t b, f2_t c) {
    f2_t d;
    asm("fma.rn.f32x2 %0, %1, %2, %3;" : "=l"(d) : "l"(a), "l"(b), "l"(c));
    return d;
}
__device__ __forceinline__ f2_t pack2(float lo, float hi) {
    f2_t d;
    asm("mov.b64 %0, {%1, %2};" : "=l"(d) : "f"(lo), "f"(hi));
    return d;
}
__device__ __forceinline__ float2 unpack2(f2_t v) {
    float2 r;
    asm("mov.b64 {%0, %1}, %2;" : "=f"(r.x), "=f"(r.y) : "l"(v));
    return r;
}

// ---------------------------------------------------------------------------
// Fused precompute: one block per batch, 576 threads. Writes g_pre.
// ---------------------------------------------------------------------------
__global__ __launch_bounds__(576)
void precompute_fused(const float* __restrict__ slots,
                      const float* __restrict__ empty_slot,
                      const float* __restrict__ Wq_w,
                      const float* __restrict__ Wq_b,
                      const float* __restrict__ Wk_w,
                      const float* __restrict__ Wk_b,
                      const float* __restrict__ out_w,
                      const float* __restrict__ out_b,
                      const float* __restrict__ dscale)
{
    __shared__ float sWk[DD][SS + 1];   // padded: conflict-free row walks
    __shared__ float sOw[DD][SS + 1];
    __shared__ float sSlot[KK][SS];
    __shared__ float sK[KK][DD];

    const int b = blockIdx.x;
    const int t = threadIdx.x;

    // Coalesced staging of Wk_w and out_w (4096 floats each)
    for (int i = t; i < DD * SS; i += 576) {
        int r = i >> 6, c = i & 63;
        sWk[r][c] = Wk_w[i];
        sOw[r][c] = out_w[i];
    }
    {   // slots_full [9][64]
        int j = t / SS, s = t % SS;
        sSlot[j][s] = (j == 0) ? empty_slot[s]
                               : slots[((size_t)b * (KK - 1) + (j - 1)) * SS + s];
    }
    __syncthreads();

    const int j = t / DD, d = t % DD;
    float kk = Wk_b[d];
    float pp = 0.f;
#pragma unroll 8
    for (int s = 0; s < SS; s++) {
        const float sv = sSlot[j][s];
        kk = fmaf(sv, sWk[d][s], kk);
        pp = fmaf(sv, sOw[d][s], pp);
    }
    sK[j][d] = kk;
    g_pre.P[b][j][d] = pp;

    // auxiliary copies (block 0 only)
    if (b == 0) {
        if (t < DD) g_pre.ob[t] = out_b[t];
        if (t == 575) g_pre.ds = __expf(dscale[0]);
    }
    __syncthreads();

    // M[j][e] = sum_d K[j][d] * Wq[d][e]   (coalesced Wq_w reads)
    const int e = d;
    float m = 0.f;
#pragma unroll 8
    for (int dd = 0; dd < DD; dd++)
        m = fmaf(sK[j][dd], Wq_w[dd * DD + e], m);
    g_pre.M[b][j][e] = m;

    if (e == 0) {
        float cc = 0.f;
        for (int dd = 0; dd < DD; dd++)
            cc = fmaf(Wq_b[dd], sK[j][dd], cc);
        g_pre.c[b][j] = cc;
    }
}

// ---------------------------------------------------------------------------
// Main kernel: one thread per point. M/P/c/ob come from the constant port —
// zero L1tex traffic for slot operands. L1 handles only essential global I/O.
// ---------------------------------------------------------------------------
__global__ __launch_bounds__(256)
void joint_decoder_main(const float* __restrict__ pf,
                        const float* __restrict__ coor,
                        float* __restrict__ xo,
                        float* __restrict__ wout,
                        float* __restrict__ sig)
{
    __shared__ float4 sCoor4[192];       // 256 pts * 3 floats, staged coalesced
    __shared__ float  sW[256 * KK];      // staged w for coalesced stores

    const int tid = threadIdx.x;
    const int p0  = blockIdx.x * 256;
    const int b   = blockIdx.x >> 10;    // 1024 blocks per batch

    if (tid < 192)
        sCoor4[tid] = reinterpret_cast<const float4*>(coor + (size_t)p0 * 3)[tid];
    __syncthreads();

    const int p = p0 + tid;

    // ---- logits: 9 dot-64s, operands from constant memory ----
    const ulonglong2* xv = reinterpret_cast<const ulonglong2*>(pf + (size_t)p * DD);
    const f2_t* M2 = reinterpret_cast<const f2_t*>(&c_pre.M[b][0][0]);  // [KK*32]
    f2_t acc[KK];
#pragma unroll
    for (int j = 0; j < KK; j++) acc[j] = 0ULL;
#pragma unroll
    for (int i = 0; i < DD / 4; i++) {
        const ulonglong2 x = xv[i];
#pragma unroll
        for (int j = 0; j < KK; j++) {
            acc[j] = fma2(x.x, M2[j * 32 + 2 * i],     acc[j]);
            acc[j] = fma2(x.y, M2[j * 32 + 2 * i + 1], acc[j]);
        }
    }
    float logit[KK];
#pragma unroll
    for (int j = 0; j < KK; j++) {
        const float2 a = unpack2(acc[j]);
        logit[j] = (a.x + a.y + c_pre.c[b][j]) * SCALE_F;
    }

    // ---- force_bg mask (coor from shared; stride-3 -> conflict-free) ----
    const float* cp = reinterpret_cast<const float*>(sCoor4) + tid * 3;
    const bool inb = (fabsf(cp[0]) <= BG_BOUND) && (fabsf(cp[1]) <= BG_BOUND) &&
                     (fabsf(cp[2]) <= BG_BOUND);

    // ---- masked softmax ----
    float mx = fmaxf(logit[0], logit[1]);
    if (inb) {
#pragma unroll
        for (int j = 2; j < KK; j++) mx = fmaxf(mx, logit[j]);
    }
    float w[KK];
    w[0] = __expf(logit[0] - mx);
    w[1] = __expf(logit[1] - mx);
    float s = w[0] + w[1];
#pragma unroll
    for (int j = 2; j < KK; j++) {
        const float e = inb ? __expf(logit[j] - mx) : 0.f;
        w[j] = e;
        s += e;
    }
    const float inv = __frcp_rn(s);
#pragma unroll
    for (int j = 0; j < KK; j++) w[j] *= inv;

    // ---- density ----
    float sg = 0.f;
#pragma unroll
    for (int j = 1; j < KK; j++) sg = fmaf(fmaxf(logit[j], 0.f), w[j], sg);

    // ---- xo = w @ P + out_b (constant-port operands, packed math) ----
    f2_t ww[KK];
#pragma unroll
    for (int j = 0; j < KK; j++) ww[j] = pack2(w[j], w[j]);

    const f2_t* P2  = reinterpret_cast<const f2_t*>(&c_pre.P[b][0][0]);
    const f2_t* Ob2 = reinterpret_cast<const f2_t*>(&c_pre.ob[0]);
    ulonglong2* xov = reinterpret_cast<ulonglong2*>(xo + (size_t)p * DD);
#pragma unroll
    for (int i = 0; i < DD / 4; i++) {
        ulonglong2 o;
        o.x = Ob2[2 * i];
        o.y = Ob2[2 * i + 1];
#pragma unroll
        for (int j = 0; j < KK; j++) {
            o.x = fma2(ww[j], P2[j * 32 + 2 * i],     o.x);
            o.y = fma2(ww[j], P2[j * 32 + 2 * i + 1], o.y);
        }
        xov[i] = o;
    }

    // ---- w out: stage in shared, store float4-coalesced ----
#pragma unroll
    for (int j = 0; j < KK; j++) sW[tid * KK + j] = w[j];   // gcd(9,32)=1: no conflicts
    sig[p] = sg * c_pre.ds;
    __syncthreads();
    {
        const float4* sw4 = reinterpret_cast<const float4*>(sW);
        float4* wg4 = reinterpret_cast<float4*>(wout + (size_t)p0 * KK);
        for (int i = tid; i < (256 * KK) / 4; i += 256)
            wg4[i] = sw4[i];
    }
}

// ---------------------------------------------------------------------------
// Launch
// ---------------------------------------------------------------------------
extern "C" void kernel_launch(void* const* d_in, const int* in_sizes, int n_in,
                              void* d_out, int out_size)
{
    const float* pf     = (const float*)d_in[0];   // point_feats [B,N,D]
    const float* slots  = (const float*)d_in[2];   // [B,K,S]
    const float* coor   = (const float*)d_in[3];   // [B,N,3]
    const float* empty  = (const float*)d_in[4];   // [1,1,S]
    const float* Wq_w   = (const float*)d_in[5];
    const float* Wq_b   = (const float*)d_in[6];
    const float* Wk_w   = (const float*)d_in[7];
    const float* Wk_b   = (const float*)d_in[8];
    const float* out_w  = (const float*)d_in[9];
    const float* out_b  = (const float*)d_in[10];
    const float* dscale = (const float*)d_in[11];

    float* out  = (float*)d_out;
    float* xo   = out;                              // [B,N,64]
    float* wout = out + (size_t)BB * NN * DD;       // [B,N,9]
    float* sig  = wout + (size_t)BB * NN * KK;      // [B,N]

    precompute_fused<<<BB, 576>>>(slots, empty, Wq_w, Wq_b, Wk_w, Wk_b,
                                  out_w, out_b, dscale);

    // Single D2D copy of the folded operands into constant memory
    // (graph-capturable memcpy node).
    void* g_pre_addr = nullptr;
    cudaGetSymbolAddress(&g_pre_addr, g_pre);
    cudaMemcpyToSymbolAsync(c_pre, g_pre_addr, sizeof(PreData), 0,
                            cudaMemcpyDeviceToDevice);

    joint_decoder_main<<<(BB * NN) / 256, 256>>>(pf, coor, xo, wout, sig);
}

// round 7
// speedup vs baseline: 2.0812x; 1.4981x over previous
#include <cuda_runtime.h>
#include <math.h>

#define BB 2
#define NN 262144
#define KK 9      // K+1 slots
#define DD 64
#define SS 64
#define BG_BOUND 1.0f
#define SCALE_F 0.125f

// ---------------------------------------------------------------------------
// Folded per-batch operands; computed on device, copied into __constant__.
// Main kernel reads them as plain C++ with warp-uniform indices so ptxas
// emits LDCU (uniform port, floor 1) instead of per-thread LDC (floor 8).
// ---------------------------------------------------------------------------
struct __align__(16) PreData {
    float M[BB][KK][DD];   // M = K @ Wq          (logit matrix)
    float P[BB][KK][DD];   // P = slots_full @ out_w^T
    float c[BB][KK];       // c = K @ Wq_b
    float ob[DD];          // out_b
    float ds;              // exp(density_scale)
};
__device__    PreData g_pre;
__constant__  PreData c_pre;

// ---------------------------------------------------------------------------
// Fused precompute: one block per batch, 576 threads. Writes g_pre.
// ---------------------------------------------------------------------------
__global__ __launch_bounds__(576)
void precompute_fused(const float* __restrict__ slots,
                      const float* __restrict__ empty_slot,
                      const float* __restrict__ Wq_w,
                      const float* __restrict__ Wq_b,
                      const float* __restrict__ Wk_w,
                      const float* __restrict__ Wk_b,
                      const float* __restrict__ out_w,
                      const float* __restrict__ out_b,
                      const float* __restrict__ dscale)
{
    __shared__ float sWk[DD][SS + 1];
    __shared__ float sOw[DD][SS + 1];
    __shared__ float sSlot[KK][SS];
    __shared__ float sK[KK][DD];

    const int b = blockIdx.x;
    const int t = threadIdx.x;

    for (int i = t; i < DD * SS; i += 576) {
        int r = i >> 6, c = i & 63;
        sWk[r][c] = Wk_w[i];
        sOw[r][c] = out_w[i];
    }
    {
        int j = t / SS, s = t % SS;
        sSlot[j][s] = (j == 0) ? empty_slot[s]
                               : slots[((size_t)b * (KK - 1) + (j - 1)) * SS + s];
    }
    __syncthreads();

    const int j = t / DD, d = t % DD;
    float kk = Wk_b[d];
    float pp = 0.f;
#pragma unroll 8
    for (int s = 0; s < SS; s++) {
        const float sv = sSlot[j][s];
        kk = fmaf(sv, sWk[d][s], kk);
        pp = fmaf(sv, sOw[d][s], pp);
    }
    sK[j][d] = kk;
    g_pre.P[b][j][d] = pp;

    if (b == 0) {
        if (t < DD) g_pre.ob[t] = out_b[t];
        if (t == 575) g_pre.ds = __expf(dscale[0]);
    }
    __syncthreads();

    const int e = d;
    float m = 0.f;
#pragma unroll 8
    for (int dd = 0; dd < DD; dd++)
        m = fmaf(sK[j][dd], Wq_w[dd * DD + e], m);
    g_pre.M[b][j][e] = m;

    if (e == 0) {
        float cc = 0.f;
        for (int dd = 0; dd < DD; dd++)
            cc = fmaf(Wq_b[dd], sK[j][dd], cc);
        g_pre.c[b][j] = cc;
    }
}

// ---------------------------------------------------------------------------
// Main kernel: 256 threads / 256 points per block.
// - pf reads and xo writes go through a shared transpose tile so every
//   global instruction is line-coalesced (4 wf/point instead of 32).
// - M/P/c/ob come from the uniform constant port (LDCU), zero L1 traffic.
// ---------------------------------------------------------------------------
__global__ __launch_bounds__(256)
void joint_decoder_main(const float* __restrict__ pf,
                        const float* __restrict__ coor,
                        float* __restrict__ xo,
                        float* __restrict__ wout,
                        float* __restrict__ sig)
{
    __shared__ float4 sT[256 * 5];       // transpose tile: 256 pts x 4 f4 (+1 pad)
    __shared__ float  sW[256 * KK];      // staged w for coalesced stores
    __shared__ float4 sCoor4[192];       // 256 pts * 3 floats

    const int tid = threadIdx.x;
    const int p0  = blockIdx.x * 256;
    const int b   = blockIdx.x >> 10;    // 1024 blocks per batch
    const int p   = p0 + tid;

    if (tid < 192)
        sCoor4[tid] = reinterpret_cast<const float4*>(coor + (size_t)p0 * 3)[tid];

    const float4* pf4 = reinterpret_cast<const float4*>(pf + (size_t)p0 * DD);

    // ---- Phase 1: logits via 4 transposed input tiles ----
    float acc[KK];
#pragma unroll
    for (int j = 0; j < KK; j++) acc[j] = 0.f;

#pragma unroll
    for (int it = 0; it < 4; it++) {
        if (it) __syncthreads();                 // previous tile fully consumed
#pragma unroll
        for (int r = 0; r < 4; r++) {            // coalesced LDG -> STS
            const int q = r * 256 + tid;
            sT[(q >> 2) * 5 + (q & 3)] = pf4[(q >> 2) * 16 + it * 4 + (q & 3)];
        }
        __syncthreads();
#pragma unroll
        for (int ii = 0; ii < 4; ii++) {
            const float4 x = sT[tid * 5 + ii];
            const int i4 = (it * 4 + ii) * 4;
#pragma unroll
            for (int j = 0; j < KK; j++) {
                acc[j] = fmaf(x.x, c_pre.M[b][j][i4 + 0],
                         fmaf(x.y, c_pre.M[b][j][i4 + 1],
                         fmaf(x.z, c_pre.M[b][j][i4 + 2],
                         fmaf(x.w, c_pre.M[b][j][i4 + 3], acc[j]))));
            }
        }
    }
    __syncthreads();                             // sT free for output phase

    float logit[KK];
#pragma unroll
    for (int j = 0; j < KK; j++)
        logit[j] = (acc[j] + c_pre.c[b][j]) * SCALE_F;

    // ---- force_bg mask (coor from shared, stride-3 conflict-free) ----
    const float* cp = reinterpret_cast<const float*>(sCoor4) + tid * 3;
    const bool inb = (fabsf(cp[0]) <= BG_BOUND) && (fabsf(cp[1]) <= BG_BOUND) &&
                     (fabsf(cp[2]) <= BG_BOUND);

    // ---- masked softmax ----
    float mx = fmaxf(logit[0], logit[1]);
    if (inb) {
#pragma unroll
        for (int j = 2; j < KK; j++) mx = fmaxf(mx, logit[j]);
    }
    float w[KK];
    w[0] = __expf(logit[0] - mx);
    w[1] = __expf(logit[1] - mx);
    float s = w[0] + w[1];
#pragma unroll
    for (int j = 2; j < KK; j++) {
        const float e = inb ? __expf(logit[j] - mx) : 0.f;
        w[j] = e;
        s += e;
    }
    const float inv = __frcp_rn(s);
#pragma unroll
    for (int j = 0; j < KK; j++) w[j] *= inv;

    // ---- density + scalar outputs ----
    float sg = 0.f;
#pragma unroll
    for (int j = 1; j < KK; j++) sg = fmaf(fmaxf(logit[j], 0.f), w[j], sg);
    sig[p] = sg * c_pre.ds;

#pragma unroll
    for (int j = 0; j < KK; j++) sW[tid * KK + j] = w[j];   // stride 9: no conflicts

    // ---- Phase 2: xo via 4 transposed output tiles ----
    float4* xo4 = reinterpret_cast<float4*>(xo + (size_t)p0 * DD);
#pragma unroll
    for (int it = 0; it < 4; it++) {
        if (it) __syncthreads();                 // previous tile fully drained
#pragma unroll
        for (int ii = 0; ii < 4; ii++) {
            const int i4 = (it * 4 + ii) * 4;
            float4 o;
            o.x = c_pre.ob[i4 + 0];
            o.y = c_pre.ob[i4 + 1];
            o.z = c_pre.ob[i4 + 2];
            o.w = c_pre.ob[i4 + 3];
#pragma unroll
            for (int j = 0; j < KK; j++) {
                o.x = fmaf(w[j], c_pre.P[b][j][i4 + 0], o.x);
                o.y = fmaf(w[j], c_pre.P[b][j][i4 + 1], o.y);
                o.z = fmaf(w[j], c_pre.P[b][j][i4 + 2], o.z);
                o.w = fmaf(w[j], c_pre.P[b][j][i4 + 3], o.w);
            }
            sT[tid * 5 + ii] = o;
        }
        __syncthreads();
#pragma unroll
        for (int r = 0; r < 4; r++) {            // LDS -> coalesced STG
            const int q = r * 256 + tid;
            xo4[(q >> 2) * 16 + it * 4 + (q & 3)] = sT[(q >> 2) * 5 + (q & 3)];
        }
    }

    // ---- w out: float4-coalesced copy (sW ordered by the O-loop barriers) ----
    {
        const float4* sw4 = reinterpret_cast<const float4*>(sW);
        float4* wg4 = reinterpret_cast<float4*>(wout + (size_t)p0 * KK);
        for (int i = tid; i < (256 * KK) / 4; i += 256)
            wg4[i] = sw4[i];
    }
}

// ---------------------------------------------------------------------------
// Launch
// ---------------------------------------------------------------------------
extern "C" void kernel_launch(void* const* d_in, const int* in_sizes, int n_in,
                              void* d_out, int out_size)
{
    const float* pf     = (const float*)d_in[0];   // point_feats [B,N,D]
    const float* slots  = (const float*)d_in[2];   // [B,K,S]
    const float* coor   = (const float*)d_in[3];   // [B,N,3]
    const float* empty  = (const float*)d_in[4];   // [1,1,S]
    const float* Wq_w   = (const float*)d_in[5];
    const float* Wq_b   = (const float*)d_in[6];
    const float* Wk_w   = (const float*)d_in[7];
    const float* Wk_b   = (const float*)d_in[8];
    const float* out_w  = (const float*)d_in[9];
    const float* out_b  = (const float*)d_in[10];
    const float* dscale = (const float*)d_in[11];

    float* out  = (float*)d_out;
    float* xo   = out;                              // [B,N,64]
    float* wout = out + (size_t)BB * NN * DD;       // [B,N,9]
    float* sig  = wout + (size_t)BB * NN * KK;      // [B,N]

    precompute_fused<<<BB, 576>>>(slots, empty, Wq_w, Wq_b, Wk_w, Wk_b,
                                  out_w, out_b, dscale);

    void* g_pre_addr = nullptr;
    cudaGetSymbolAddress(&g_pre_addr, g_pre);
    cudaMemcpyToSymbolAsync(c_pre, g_pre_addr, sizeof(PreData), 0,
                            cudaMemcpyDeviceToDevice);

    joint_decoder_main<<<(BB * NN) / 256, 256>>>(pf, coor, xo, wout, sig);
}

// round 8
// speedup vs baseline: 2.3272x; 1.1182x over previous
#include <cuda_runtime.h>
#include <math.h>

#define BB 2
#define NN 262144
#define KK 9      // K+1 slots
#define DD 64
#define SS 64
#define BG_BOUND 1.0f
#define SCALE_F 0.125f

// ---------------------------------------------------------------------------
// Folded per-batch operands; computed on device, copied into __constant__.
// Warp-uniform indices in the main kernel -> LDCU (uniform const port).
// ---------------------------------------------------------------------------
struct __align__(16) PreData {
    float M[BB][KK][DD];   // M = K @ Wq          (logit matrix)
    float P[BB][KK][DD];   // P = slots_full @ out_w^T
    float c[BB][KK];       // c = K @ Wq_b
    float ob[DD];          // out_b
    float ds;              // exp(density_scale)
};
__device__    PreData g_pre;
__constant__  PreData c_pre;

// ---------------------------------------------------------------------------
// Precompute: one block per (batch, slot) pair -> 18 blocks, 64 threads.
// ---------------------------------------------------------------------------
__global__ __launch_bounds__(64)
void precompute(const float* __restrict__ slots,
                const float* __restrict__ empty_slot,
                const float* __restrict__ Wq_w,
                const float* __restrict__ Wq_b,
                const float* __restrict__ Wk_w,
                const float* __restrict__ Wk_b,
                const float* __restrict__ out_w,
                const float* __restrict__ out_b,
                const float* __restrict__ dscale)
{
    __shared__ float sSlot[SS];
    __shared__ float sK[DD];

    const int b = blockIdx.x / KK;
    const int j = blockIdx.x % KK;
    const int d = threadIdx.x;

    sSlot[d] = (j == 0) ? empty_slot[d]
                        : slots[((size_t)b * (KK - 1) + (j - 1)) * SS + d];
    __syncthreads();

    // K[d] and P[d]: per-thread row walks of Wk_w / out_w (L2-resident, MLP 16)
    const float4* wk4 = reinterpret_cast<const float4*>(Wk_w  + d * SS);
    const float4* ow4 = reinterpret_cast<const float4*>(out_w + d * SS);
    float kk = Wk_b[d];
    float pp = 0.f;
#pragma unroll
    for (int i = 0; i < SS / 4; i++) {
        const float4 wv = wk4[i];
        const float4 ov = ow4[i];
        const float s0 = sSlot[4 * i], s1 = sSlot[4 * i + 1];
        const float s2 = sSlot[4 * i + 2], s3 = sSlot[4 * i + 3];
        kk = fmaf(s0, wv.x, fmaf(s1, wv.y, fmaf(s2, wv.z, fmaf(s3, wv.w, kk))));
        pp = fmaf(s0, ov.x, fmaf(s1, ov.y, fmaf(s2, ov.z, fmaf(s3, ov.w, pp))));
    }
    sK[d] = kk;
    g_pre.P[b][j][d] = pp;

    if (blockIdx.x == 0) {
        g_pre.ob[d] = out_b[d];
        if (d == 0) g_pre.ds = __expf(dscale[0]);
    }
    __syncthreads();

    // M[j][e=d] = sum_dd K[dd] * Wq[dd][d]  (coalesced Wq_w reads)
    float m = 0.f;
#pragma unroll 8
    for (int dd = 0; dd < DD; dd++)
        m = fmaf(sK[dd], Wq_w[dd * DD + d], m);
    g_pre.M[b][j][d] = m;

    if (d == 0) {
        float cc = 0.f;
        for (int dd = 0; dd < DD; dd++)
            cc = fmaf(Wq_b[dd], sK[dd], cc);
        g_pre.c[b][j] = cc;
    }
}

// ---------------------------------------------------------------------------
// Main kernel: 256 threads / 256 points per block.
// Transpose tile sT4[4][258]: plane stride 258 f4 == 2 (mod 8) bank-quads,
// so staging stores [q&3][q>>2], compute accesses [ii][tid], and both
// phase-2 patterns are all exactly at the 4-wavefront .128 floor.
// ---------------------------------------------------------------------------
__global__ __launch_bounds__(256)
void joint_decoder_main(const float* __restrict__ pf,
                        const float* __restrict__ coor,
                        float* __restrict__ xo,
                        float* __restrict__ wout,
                        float* __restrict__ sig)
{
    __shared__ float4 sT4[4][258];       // conflict-free transpose tile
    __shared__ float  sW[256 * KK];      // staged w for coalesced stores
    __shared__ float4 sCoor4[192];       // 256 pts * 3 floats

    const int tid = threadIdx.x;
    const int p0  = blockIdx.x * 256;
    const int b   = blockIdx.x >> 10;    // 1024 blocks per batch
    const int p   = p0 + tid;

    if (tid < 192)
        sCoor4[tid] = reinterpret_cast<const float4*>(coor + (size_t)p0 * 3)[tid];

    const float4* pf4 = reinterpret_cast<const float4*>(pf + (size_t)p0 * DD);

    // ---- Phase 1: logits via 4 transposed input tiles ----
    float acc[KK];
#pragma unroll
    for (int j = 0; j < KK; j++) acc[j] = 0.f;

#pragma unroll
    for (int it = 0; it < 4; it++) {
        if (it) __syncthreads();                 // previous tile fully consumed
#pragma unroll
        for (int r = 0; r < 4; r++) {
            const int q = r * 256 + tid;
            sT4[q & 3][q >> 2] = pf4[(q >> 2) * 16 + it * 4 + (q & 3)];
        }
        __syncthreads();
#pragma unroll
        for (int ii = 0; ii < 4; ii++) {
            const float4 x = sT4[ii][tid];
            const int i4 = (it * 4 + ii) * 4;
#pragma unroll
            for (int j = 0; j < KK; j++) {
                acc[j] = fmaf(x.x, c_pre.M[b][j][i4 + 0],
                         fmaf(x.y, c_pre.M[b][j][i4 + 1],
                         fmaf(x.z, c_pre.M[b][j][i4 + 2],
                         fmaf(x.w, c_pre.M[b][j][i4 + 3], acc[j]))));
            }
        }
    }
    __syncthreads();                             // sT4 free for output phase

    float logit[KK];
#pragma unroll
    for (int j = 0; j < KK; j++)
        logit[j] = (acc[j] + c_pre.c[b][j]) * SCALE_F;

    // ---- force_bg mask (coor from shared, stride-3 conflict-free) ----
    const float* cp = reinterpret_cast<const float*>(sCoor4) + tid * 3;
    const bool inb = (fabsf(cp[0]) <= BG_BOUND) && (fabsf(cp[1]) <= BG_BOUND) &&
                     (fabsf(cp[2]) <= BG_BOUND);

    // ---- masked softmax ----
    float mx = fmaxf(logit[0], logit[1]);
    if (inb) {
#pragma unroll
        for (int j = 2; j < KK; j++) mx = fmaxf(mx, logit[j]);
    }
    float w[KK];
    w[0] = __expf(logit[0] - mx);
    w[1] = __expf(logit[1] - mx);
    float s = w[0] + w[1];
#pragma unroll
    for (int j = 2; j < KK; j++) {
        const float e = inb ? __expf(logit[j] - mx) : 0.f;
        w[j] = e;
        s += e;
    }
    const float inv = __frcp_rn(s);
#pragma unroll
    for (int j = 0; j < KK; j++) w[j] *= inv;

    // ---- density + scalar outputs ----
    float sg = 0.f;
#pragma unroll
    for (int j = 1; j < KK; j++) sg = fmaf(fmaxf(logit[j], 0.f), w[j], sg);
    sig[p] = sg * c_pre.ds;

#pragma unroll
    for (int j = 0; j < KK; j++) sW[tid * KK + j] = w[j];   // stride 9: no conflicts

    // ---- Phase 2: xo via 4 transposed output tiles ----
    float4* xo4 = reinterpret_cast<float4*>(xo + (size_t)p0 * DD);
#pragma unroll
    for (int it = 0; it < 4; it++) {
        if (it) __syncthreads();                 // previous tile fully drained
#pragma unroll
        for (int ii = 0; ii < 4; ii++) {
            const int i4 = (it * 4 + ii) * 4;
            float4 o;
            o.x = c_pre.ob[i4 + 0];
            o.y = c_pre.ob[i4 + 1];
            o.z = c_pre.ob[i4 + 2];
            o.w = c_pre.ob[i4 + 3];
#pragma unroll
            for (int j = 0; j < KK; j++) {
                o.x = fmaf(w[j], c_pre.P[b][j][i4 + 0], o.x);
                o.y = fmaf(w[j], c_pre.P[b][j][i4 + 1], o.y);
                o.z = fmaf(w[j], c_pre.P[b][j][i4 + 2], o.z);
                o.w = fmaf(w[j], c_pre.P[b][j][i4 + 3], o.w);
            }
            sT4[ii][tid] = o;
        }
        __syncthreads();
#pragma unroll
        for (int r = 0; r < 4; r++) {
            const int q = r * 256 + tid;
            xo4[(q >> 2) * 16 + it * 4 + (q & 3)] = sT4[q & 3][q >> 2];
        }
    }

    // ---- w out: float4-coalesced copy (ordered by the phase-2 barriers) ----
    {
        const float4* sw4 = reinterpret_cast<const float4*>(sW);
        float4* wg4 = reinterpret_cast<float4*>(wout + (size_t)p0 * KK);
        for (int i = tid; i < (256 * KK) / 4; i += 256)
            wg4[i] = sw4[i];
    }
}

// ---------------------------------------------------------------------------
// Launch
// ---------------------------------------------------------------------------
extern "C" void kernel_launch(void* const* d_in, const int* in_sizes, int n_in,
                              void* d_out, int out_size)
{
    const float* pf     = (const float*)d_in[0];   // point_feats [B,N,D]
    const float* slots  = (const float*)d_in[2];   // [B,K,S]
    const float* coor   = (const float*)d_in[3];   // [B,N,3]
    const float* empty  = (const float*)d_in[4];   // [1,1,S]
    const float* Wq_w   = (const float*)d_in[5];
    const float* Wq_b   = (const float*)d_in[6];
    const float* Wk_w   = (const float*)d_in[7];
    const float* Wk_b   = (const float*)d_in[8];
    const float* out_w  = (const float*)d_in[9];
    const float* out_b  = (const float*)d_in[10];
    const float* dscale = (const float*)d_in[11];

    float* out  = (float*)d_out;
    float* xo   = out;                              // [B,N,64]
    float* wout = out + (size_t)BB * NN * DD;       // [B,N,9]
    float* sig  = wout + (size_t)BB * NN * KK;      // [B,N]

    precompute<<<BB * KK, 64>>>(slots, empty, Wq_w, Wq_b, Wk_w, Wk_b,
                                out_w, out_b, dscale);

    void* g_pre_addr = nullptr;
    cudaGetSymbolAddress(&g_pre_addr, g_pre);
    cudaMemcpyToSymbolAsync(c_pre, g_pre_addr, sizeof(PreData), 0,
                            cudaMemcpyDeviceToDevice);

    joint_decoder_main<<<(BB * NN) / 256, 256>>>(pf, coor, xo, wout, sig);
}